// round 4
// baseline (speedup 1.0000x reference)
#include <cuda_runtime.h>
#include <math.h>

// ---------------- problem constants ----------------
namespace cfg {
constexpr int Cc = 192, NHc = 6, Nn = 49;
constexpr int Tt = 100352;           // 32*56*56 tokens
constexpr int HID = 768, QKVN = 576;
constexpr float SCALE = 0.17677669529663689f;   // 1/sqrt(32)
constexpr float EPSc = 1e-5f;
}
using namespace cfg;

// ---------------- scratch (static device allocs) ----------------
__device__ float g_ln1[(size_t)Tt * Cc];
__device__ float g_qkv[(size_t)Tt * QKVN];
__device__ float g_att[(size_t)Tt * Cc];
__device__ float g_h  [(size_t)Tt * Cc];
__device__ float g_ln2[(size_t)Tt * Cc];
__device__ float g_a1 [(size_t)Tt * HID];
__device__ float g_wr [442368];   // rounded weights: qkv|proj|fc1|fc2
constexpr size_t WO_QKV = 0, WO_PROJ = 110592, WO_FC1 = 147456, WO_FC2 = 294912;

// ---------------- helpers ----------------
__device__ __forceinline__ float to_tf32(float x) {
    unsigned int u;
    asm("cvt.rna.tf32.f32 %0, %1;" : "=r"(u) : "f"(x));
    return __uint_as_float(u);
}
__device__ __forceinline__ void cp16(unsigned int s, const void* g) {
    asm volatile("cp.async.cg.shared.global [%0], [%1], 16;" :: "r"(s), "l"(g));
}
__device__ __forceinline__ void cp_commit() {
    asm volatile("cp.async.commit_group;" ::: "memory");
}
template <int N>
__device__ __forceinline__ void cp_wait() {
    asm volatile("cp.async.wait_group %0;" :: "n"(N) : "memory");
}
__device__ __forceinline__ void mma8(float* c, const unsigned int* a,
                                     const unsigned int* b) {
    asm volatile(
        "mma.sync.aligned.m16n8k8.row.col.f32.tf32.tf32.f32 "
        "{%0,%1,%2,%3},{%4,%5,%6,%7},{%8,%9},{%0,%1,%2,%3};"
        : "+f"(c[0]), "+f"(c[1]), "+f"(c[2]), "+f"(c[3])
        : "r"(a[0]), "r"(a[1]), "r"(a[2]), "r"(a[3]), "r"(b[0]), "r"(b[1]));
}
__device__ __forceinline__ void fma2(unsigned long long& d,
                                     unsigned long long a,
                                     unsigned long long b) {
    asm("fma.rn.f32x2 %0, %1, %2, %0;" : "+l"(d) : "l"(a), "l"(b));
}
__device__ __forceinline__ float sum2(unsigned long long a) {
    return __uint_as_float((unsigned int)a) +
           __uint_as_float((unsigned int)(a >> 32));
}

// ---------------- weight tf32 pre-round (all four in one launch) ------
__global__ void round_kernel(const float* __restrict__ s0, const float* __restrict__ s1,
                             const float* __restrict__ s2, const float* __restrict__ s3,
                             float* __restrict__ dst) {
    int i = blockIdx.x * 256 + threadIdx.x;           // float4 index, total 110592
    if (i >= 110592) return;
    const float* src; int off;
    if (i < 27648)      { src = s0; off = i; }
    else if (i < 36864) { src = s1; off = i - 27648; }
    else if (i < 73728) { src = s2; off = i - 36864; }
    else                { src = s3; off = i - 73728; }
    float4 v = ((const float4*)src)[off];
    v.x = to_tf32(v.x); v.y = to_tf32(v.y);
    v.z = to_tf32(v.z); v.w = to_tf32(v.w);
    ((float4*)dst)[i] = v;
}

// ---------------- LayerNorm (one warp per token, tf32-rounded out) -------
__global__ void __launch_bounds__(256, 1)
ln_kernel(const float* __restrict__ src, const float* __restrict__ g,
          const float* __restrict__ b, float* __restrict__ dst) {
    const int wp = threadIdx.x >> 5, lane = threadIdx.x & 31;
    const int t = blockIdx.x * 8 + wp;
    const float* r = src + (size_t)t * Cc;
    float vals[6], s = 0.f;
    #pragma unroll
    for (int j = 0; j < 6; j++) { vals[j] = r[lane + 32 * j]; s += vals[j]; }
    #pragma unroll
    for (int o = 16; o; o >>= 1) s += __shfl_xor_sync(~0u, s, o);
    float mu = s * (1.f / 192.f), s2 = 0.f;
    #pragma unroll
    for (int j = 0; j < 6; j++) { float d = vals[j] - mu; s2 += d * d; }
    #pragma unroll
    for (int o = 16; o; o >>= 1) s2 += __shfl_xor_sync(~0u, s2, o);
    float rs = rsqrtf(s2 * (1.f / 192.f) + EPSc);
    float* w = dst + (size_t)t * Cc;
    #pragma unroll
    for (int j = 0; j < 6; j++) {
        int cc = lane + 32 * j;
        w[cc] = to_tf32((vals[j] - mu) * rs * g[cc] + b[cc]);
    }
}

// ---------------- tf32 tensor-core GEMM ----------------
// C[M,N] = A[M,K] @ B[N,K]^T (+bias, epilogue). CTA tile 128x128, 128 thr
// (2x2 warps, warp tile 64x64), K chunks of 32, 3-stage cp.async pipeline.
// EPI: 0 = qkv (scale cols<192), 1 = residual add, 2 = gelu + tf32 round
constexpr int AS_W = 128 * 36, BS_W = 128 * 36, BUF_W = AS_W + BS_W;  // 9216
constexpr int GEMM_SMEM = BUF_W * 3 * 4;   // 110592 B (3 stages)

template <int NCOLS, int KDIM, int EPI>
__global__ void __launch_bounds__(128, 2)
gemm_kernel(const float* __restrict__ A, const float* __restrict__ Bw,
            const float* __restrict__ bias, const float* __restrict__ res,
            float* __restrict__ out) {
    extern __shared__ float smem_g[];
    const int tid = threadIdx.x, wid = tid >> 5, lane = tid & 31;
    const int wm = wid >> 1, wn = wid & 1;
    const int n0 = blockIdx.x * 128;
    const int m0 = blockIdx.y * 128;
    constexpr int NC = KDIM / 32;
    const unsigned int sbase = (unsigned int)__cvta_generic_to_shared(smem_g);

    auto stage = [&](int buf, int c) {
        const int k0 = c * 32;
        const unsigned int sa = sbase + (unsigned)(buf * BUF_W) * 4u;
        #pragma unroll
        for (int i = 0; i < 8; i++) {
            int s = tid + i * 128;          // 1024 A segs (128 rows x 8 quads)
            int row = s >> 3, cq = s & 7;
            cp16(sa + (unsigned)(row * 36 + cq * 4) * 4u,
                 A + (size_t)(m0 + row) * KDIM + k0 + cq * 4);
        }
        const unsigned int sb = sbase + (unsigned)(buf * BUF_W + AS_W) * 4u;
        #pragma unroll
        for (int i = 0; i < 8; i++) {
            int s = tid + i * 128;          // 1024 B segs
            int row = s >> 3, cq = s & 7;
            int gn = n0 + row; if (gn > NCOLS - 1) gn = NCOLS - 1;
            cp16(sb + (unsigned)(row * 36 + cq * 4) * 4u,
                 Bw + (size_t)gn * KDIM + k0 + cq * 4);
        }
    };

    float acc[4][8][4];
    #pragma unroll
    for (int mi = 0; mi < 4; mi++)
        #pragma unroll
        for (int ni = 0; ni < 8; ni++)
            #pragma unroll
            for (int q = 0; q < 4; q++) acc[mi][ni][q] = 0.f;

    stage(0, 0); cp_commit();
    stage(1, 1); cp_commit();

    const int la = lane >> 2, lb = lane & 3;
    for (int ch = 0; ch < NC; ch++) {
        if (ch + 1 < NC) cp_wait<1>(); else cp_wait<0>();
        __syncthreads();                  // data visible; prev reads done
        if (ch + 2 < NC) { stage((ch + 2) % 3, ch + 2); cp_commit(); }
        const unsigned int* As = (const unsigned int*)(smem_g + (ch % 3) * BUF_W);
        const unsigned int* Bs = As + AS_W;
        #pragma unroll
        for (int kk = 0; kk < 4; kk++) {
            unsigned int a[4][4], b[8][2];
            const int ac = kk * 8 + lb;
            #pragma unroll
            for (int mi = 0; mi < 4; mi++) {
                int base = (wm * 64 + mi * 16 + la) * 36 + ac;
                a[mi][0] = As[base];           a[mi][1] = As[base + 8 * 36];
                a[mi][2] = As[base + 4];       a[mi][3] = As[base + 8 * 36 + 4];
            }
            #pragma unroll
            for (int ni = 0; ni < 8; ni++) {
                int base = (wn * 64 + ni * 8 + la) * 36 + ac;
                b[ni][0] = Bs[base];           b[ni][1] = Bs[base + 4];
            }
            #pragma unroll
            for (int mi = 0; mi < 4; mi++)
                #pragma unroll
                for (int ni = 0; ni < 8; ni++) mma8(acc[mi][ni], a[mi], b[ni]);
        }
        __syncthreads();
    }

    // ---- epilogue ----
    const int er = m0 + wm * 64 + la;
    const int ec = n0 + wn * 64 + lb * 2;
    #pragma unroll
    for (int ni = 0; ni < 8; ni++) {
        const int col = ec + ni * 8;
        if (col < NCOLS) {
            const float b0 = bias[col], b1 = bias[col + 1];
            #pragma unroll
            for (int mi = 0; mi < 4; mi++) {
                const int r0 = er + mi * 16;
                #pragma unroll
                for (int half = 0; half < 2; half++) {
                    const int r = r0 + half * 8;
                    float v0 = acc[mi][ni][half * 2 + 0] + b0;
                    float v1 = acc[mi][ni][half * 2 + 1] + b1;
                    const size_t off = (size_t)r * NCOLS + col;
                    float2 o;
                    if (EPI == 0) {             // qkv: scale q columns
                        if (col < 192) { v0 *= SCALE; v1 *= SCALE; }
                        o.x = v0; o.y = v1;
                    } else if (EPI == 1) {      // residual add
                        float2 rv = *(const float2*)(res + off);
                        o.x = rv.x + v0; o.y = rv.y + v1;
                    } else {                    // exact GELU, tf32 round
                        o.x = to_tf32(v0 * normcdff(v0));
                        o.y = to_tf32(v1 * normcdff(v1));
                    }
                    *(float2*)(out + off) = o;
                }
            }
        }
    }
}

// ---------------- attention (per shifted window) ----------------
// smem: V (6 heads, stride 36) + one head's probabilities + rpb + tok/lab.
// K rows live in registers per warp-task; q/k read from gmem (L1-resident).
constexpr int VS = 36;                          // v row stride (16B aligned)
constexpr int OV = 0;                           // 6*49*36 = 10584
constexpr int OSC = 10584;                      // 49*50  = 2450
constexpr int ORPB = OSC + 2450;                // 1014
constexpr int OTOK = ORPB + 1014;               // 49
constexpr int OLAB = OTOK + 49;                 // 49
constexpr int ATT_SMEM_W = OLAB + 49;           // 14146 words
constexpr int ATT_SMEM = ATT_SMEM_W * 4;        // 56584 B

__global__ void __launch_bounds__(256)
attn_kernel(const float* __restrict__ qkv, const float* __restrict__ rpbt,
            float* __restrict__ att) {
    extern __shared__ float sm[];
    int* tok = (int*)(sm + OTOK);
    int* lab = (int*)(sm + OLAB);
    const int tid = threadIdx.x, wp = tid >> 5, lane = tid & 31;
    const int bw = blockIdx.x, img = bw >> 6, win = bw & 63;
    const int wr = win >> 3, wcw = win & 7;

    if (tid < Nn) {
        int r = tid / 7, c = tid % 7;
        int sy = (wr * 7 + r + 3) % 56, sx = (wcw * 7 + c + 3) % 56;
        tok[tid] = img * 3136 + sy * 56 + sx;
        int y = wr * 7 + r, xx = wcw * 7 + c;
        lab[tid] = ((y < 49) ? 0 : (y < 53 ? 1 : 2)) * 3 +
                   ((xx < 49) ? 0 : (xx < 53 ? 1 : 2));
    }
    for (int i = tid; i < 1014; i += 256) sm[ORPB + i] = rpbt[i];
    __syncthreads();

    // stage V (all heads) into [h*49+i][36]
    for (int e = tid; e < 49 * 48; e += 256) {
        int i = e / 48, c4 = e - i * 48;
        int col = c4 * 4, h = col >> 5, d = col & 31;
        float4 v = *(const float4*)(qkv + (size_t)tok[i] * QKVN + 384 + col);
        *(float4*)(sm + OV + (h * 49 + i) * VS + d) = v;
    }
    __syncthreads();

    for (int h = 0; h < NHc; h++) {
        // ---- scores + softmax: warp-task per ib (7 queries), K in regs ----
        if (wp < 7) {
            const int ib = wp;
            // K rows for this head: lane holds j0=lane, j1=lane+32 (if <49)
            unsigned long long k0r[16], k1r[16];
            {
                const unsigned long long* kp = (const unsigned long long*)(
                    qkv + (size_t)tok[lane] * QKVN + 192 + h * 32);
                #pragma unroll
                for (int p = 0; p < 16; p++) k0r[p] = kp[p];
            }
            if (lane < 17) {
                const unsigned long long* kp = (const unsigned long long*)(
                    qkv + (size_t)tok[lane + 32] * QKVN + 192 + h * 32);
                #pragma unroll
                for (int p = 0; p < 16; p++) k1r[p] = kp[p];
            }
            int rj0 = lane / 7, cj0 = lane % 7, lj0 = lab[lane];
            int j1 = lane + 32;
            int rj1 = j1 / 7, cj1 = j1 % 7;
            int lj1 = (lane < 17) ? lab[j1] : 0;

            #pragma unroll
            for (int ii = 0; ii < 7; ii++) {
                int i = ib * 7 + ii;
                const unsigned long long* qp = (const unsigned long long*)(
                    qkv + (size_t)tok[i] * QKVN + h * 32);
                unsigned long long a0 = 0ull, a1 = 0ull;
                #pragma unroll
                for (int p = 0; p < 16; p++) {
                    unsigned long long qv = qp[p];
                    fma2(a0, qv, k0r[p]);
                    fma2(a1, qv, k1r[p]);
                }
                int ri = i / 7, ci = i % 7, li = lab[i];
                float s0 = sum2(a0) +
                    sm[ORPB + ((ri - rj0 + 6) * 13 + (ci - cj0 + 6)) * 6 + h];
                if (lj0 != li) s0 -= 100.f;
                float s1;
                if (lane < 17) {
                    s1 = sum2(a1) +
                        sm[ORPB + ((ri - rj1 + 6) * 13 + (ci - cj1 + 6)) * 6 + h];
                    if (lj1 != li) s1 -= 100.f;
                } else s1 = __int_as_float(0xff800000);

                float m = fmaxf(s0, s1);
                #pragma unroll
                for (int o = 16; o; o >>= 1)
                    m = fmaxf(m, __shfl_xor_sync(~0u, m, o));
                float e0 = __expf(s0 - m);
                float e1 = (lane < 17) ? __expf(s1 - m) : 0.f;
                float ssum = e0 + e1;
                #pragma unroll
                for (int o = 16; o; o >>= 1)
                    ssum += __shfl_xor_sync(~0u, ssum, o);
                float inv = __frcp_rn(ssum);
                sm[OSC + i * 50 + lane] = e0 * inv;
                if (lane < 17) sm[OSC + i * 50 + j1] = e1 * inv;
            }
        }
        __syncthreads();

        // ---- P @ V: warp-task per ib; lane = (jhalf, dquad) ----
        if (wp < 7) {
            const int ib = wp;
            const int dq = lane & 7, jh = lane >> 3;
            const int jbeg = jh * 13, jend = (jh < 3) ? jbeg + 13 : 49;
            float acc[7][4];
            #pragma unroll
            for (int ii = 0; ii < 7; ii++)
                #pragma unroll
                for (int q = 0; q < 4; q++) acc[ii][q] = 0.f;
            for (int j = jbeg; j < jend; j++) {
                float4 vv = *(const float4*)(sm + OV + (h * 49 + j) * VS + dq * 4);
                #pragma unroll
                for (int ii = 0; ii < 7; ii++) {
                    float p = sm[OSC + (ib * 7 + ii) * 50 + j];
                    acc[ii][0] += p * vv.x; acc[ii][1] += p * vv.y;
                    acc[ii][2] += p * vv.z; acc[ii][3] += p * vv.w;
                }
            }
            #pragma unroll
            for (int ii = 0; ii < 7; ii++)
                #pragma unroll
                for (int q = 0; q < 4; q++) {
                    acc[ii][q] += __shfl_xor_sync(~0u, acc[ii][q], 8);
                    acc[ii][q] += __shfl_xor_sync(~0u, acc[ii][q], 16);
                }
            if (jh == 0) {
                #pragma unroll
                for (int ii = 0; ii < 7; ii++) {
                    int i = ib * 7 + ii;
                    float4 o;
                    o.x = to_tf32(acc[ii][0]); o.y = to_tf32(acc[ii][1]);
                    o.z = to_tf32(acc[ii][2]); o.w = to_tf32(acc[ii][3]);
                    *(float4*)(att + (size_t)tok[i] * Cc + h * 32 + dq * 4) = o;
                }
            }
        }
        __syncthreads();
    }
}

// ---------------- launch ----------------
extern "C" void kernel_launch(void* const* d_in, const int* in_sizes, int n_in,
                              void* d_out, int out_size) {
    const float* x     = (const float*)d_in[0];
    const float* n1g   = (const float*)d_in[1];
    const float* n1b   = (const float*)d_in[2];
    const float* qkvw  = (const float*)d_in[3];
    const float* qkvb  = (const float*)d_in[4];
    const float* projw = (const float*)d_in[5];
    const float* projb = (const float*)d_in[6];
    const float* rpbt  = (const float*)d_in[7];
    const float* n2g   = (const float*)d_in[8];
    const float* n2b   = (const float*)d_in[9];
    const float* fc1w  = (const float*)d_in[10];
    const float* fc1b  = (const float*)d_in[11];
    const float* fc2w  = (const float*)d_in[12];
    const float* fc2b  = (const float*)d_in[13];
    float* out = (float*)d_out;

    float *ln1, *qkvs, *atts, *hs, *ln2, *a1, *wr;
    cudaGetSymbolAddress((void**)&ln1,  g_ln1);
    cudaGetSymbolAddress((void**)&qkvs, g_qkv);
    cudaGetSymbolAddress((void**)&atts, g_att);
    cudaGetSymbolAddress((void**)&hs,   g_h);
    cudaGetSymbolAddress((void**)&ln2,  g_ln2);
    cudaGetSymbolAddress((void**)&a1,   g_a1);
    cudaGetSymbolAddress((void**)&wr,   g_wr);

    cudaFuncSetAttribute(gemm_kernel<QKVN, Cc, 0>,
                         cudaFuncAttributeMaxDynamicSharedMemorySize, GEMM_SMEM);
    cudaFuncSetAttribute(gemm_kernel<Cc, Cc, 1>,
                         cudaFuncAttributeMaxDynamicSharedMemorySize, GEMM_SMEM);
    cudaFuncSetAttribute(gemm_kernel<HID, Cc, 2>,
                         cudaFuncAttributeMaxDynamicSharedMemorySize, GEMM_SMEM);
    cudaFuncSetAttribute(gemm_kernel<Cc, HID, 1>,
                         cudaFuncAttributeMaxDynamicSharedMemorySize, GEMM_SMEM);
    cudaFuncSetAttribute(attn_kernel,
                         cudaFuncAttributeMaxDynamicSharedMemorySize, ATT_SMEM);

    round_kernel<<<(110592 + 255) / 256, 256>>>(qkvw, projw, fc1w, fc2w, wr);

    ln_kernel<<<Tt / 8, 256>>>(x, n1g, n1b, ln1);
    gemm_kernel<QKVN, Cc, 0><<<dim3(5, 784), 128, GEMM_SMEM>>>(
        ln1, wr + WO_QKV, qkvb, nullptr, qkvs);
    attn_kernel<<<2048, 256, ATT_SMEM>>>(qkvs, rpbt, atts);
    gemm_kernel<Cc, Cc, 1><<<dim3(2, 784), 128, GEMM_SMEM>>>(
        atts, wr + WO_PROJ, projb, x, hs);
    ln_kernel<<<Tt / 8, 256>>>(hs, n2g, n2b, ln2);
    gemm_kernel<HID, Cc, 2><<<dim3(6, 784), 128, GEMM_SMEM>>>(
        ln2, wr + WO_FC1, fc1b, nullptr, a1);
    gemm_kernel<Cc, HID, 1><<<dim3(2, 784), 128, GEMM_SMEM>>>(
        a1, wr + WO_FC2, fc2b, hs, out);
}

// round 5
// speedup vs baseline: 1.4190x; 1.4190x over previous
#include <cuda_runtime.h>
#include <math.h>

// ---------------- problem constants ----------------
namespace cfg {
constexpr int Cc = 192, NHc = 6, Nn = 49;
constexpr int Tt = 100352;           // 32*56*56 tokens
constexpr int HID = 768, QKVN = 576;
constexpr float SCALE = 0.17677669529663689f;   // 1/sqrt(32)
constexpr float EPSc = 1e-5f;
}
using namespace cfg;

// ---------------- scratch (static device allocs) ----------------
__device__ float g_ln1[(size_t)Tt * Cc];
__device__ float g_qkv[(size_t)Tt * QKVN];
__device__ float g_att[(size_t)Tt * Cc];
__device__ float g_h  [(size_t)Tt * Cc];
__device__ float g_ln2[(size_t)Tt * Cc];
__device__ float g_a1 [(size_t)Tt * HID];
__device__ float g_wr [442368];   // rounded weights: qkv|proj|fc1|fc2
constexpr size_t WO_QKV = 0, WO_PROJ = 110592, WO_FC1 = 147456, WO_FC2 = 294912;

// ---------------- helpers ----------------
__device__ __forceinline__ float to_tf32(float x) {
    unsigned int u;
    asm("cvt.rna.tf32.f32 %0, %1;" : "=r"(u) : "f"(x));
    return __uint_as_float(u);
}
__device__ __forceinline__ void cp16(unsigned int s, const void* g) {
    asm volatile("cp.async.cg.shared.global [%0], [%1], 16;" :: "r"(s), "l"(g));
}
__device__ __forceinline__ void cp_commit() {
    asm volatile("cp.async.commit_group;" ::: "memory");
}
template <int N>
__device__ __forceinline__ void cp_wait() {
    asm volatile("cp.async.wait_group %0;" :: "n"(N) : "memory");
}
__device__ __forceinline__ void mma8(float* c, const unsigned int* a,
                                     const unsigned int* b) {
    asm volatile(
        "mma.sync.aligned.m16n8k8.row.col.f32.tf32.tf32.f32 "
        "{%0,%1,%2,%3},{%4,%5,%6,%7},{%8,%9},{%0,%1,%2,%3};"
        : "+f"(c[0]), "+f"(c[1]), "+f"(c[2]), "+f"(c[3])
        : "r"(a[0]), "r"(a[1]), "r"(a[2]), "r"(a[3]), "r"(b[0]), "r"(b[1]));
}
__device__ __forceinline__ void fma2(unsigned long long& d,
                                     unsigned long long a,
                                     unsigned long long b) {
    asm("fma.rn.f32x2 %0, %1, %2, %0;" : "+l"(d) : "l"(a), "l"(b));
}
__device__ __forceinline__ float sum2(unsigned long long a) {
    return __uint_as_float((unsigned int)a) +
           __uint_as_float((unsigned int)(a >> 32));
}

// ---------------- weight tf32 pre-round (all four in one launch) ------
__global__ void round_kernel(const float* __restrict__ s0, const float* __restrict__ s1,
                             const float* __restrict__ s2, const float* __restrict__ s3,
                             float* __restrict__ dst) {
    int i = blockIdx.x * 256 + threadIdx.x;           // float4 index, total 110592
    if (i >= 110592) return;
    const float* src; int off;
    if (i < 27648)      { src = s0; off = i; }
    else if (i < 36864) { src = s1; off = i - 27648; }
    else if (i < 73728) { src = s2; off = i - 36864; }
    else                { src = s3; off = i - 73728; }
    float4 v = ((const float4*)src)[off];
    v.x = to_tf32(v.x); v.y = to_tf32(v.y);
    v.z = to_tf32(v.z); v.w = to_tf32(v.w);
    ((float4*)dst)[i] = v;
}

// ---------------- LayerNorm (one warp per token, tf32-rounded out) -------
__global__ void __launch_bounds__(256, 1)
ln_kernel(const float* __restrict__ src, const float* __restrict__ g,
          const float* __restrict__ b, float* __restrict__ dst) {
    const int wp = threadIdx.x >> 5, lane = threadIdx.x & 31;
    const int t = blockIdx.x * 8 + wp;
    const float* r = src + (size_t)t * Cc;
    float vals[6], s = 0.f;
    #pragma unroll
    for (int j = 0; j < 6; j++) { vals[j] = r[lane + 32 * j]; s += vals[j]; }
    #pragma unroll
    for (int o = 16; o; o >>= 1) s += __shfl_xor_sync(~0u, s, o);
    float mu = s * (1.f / 192.f), s2 = 0.f;
    #pragma unroll
    for (int j = 0; j < 6; j++) { float d = vals[j] - mu; s2 += d * d; }
    #pragma unroll
    for (int o = 16; o; o >>= 1) s2 += __shfl_xor_sync(~0u, s2, o);
    float rs = rsqrtf(s2 * (1.f / 192.f) + EPSc);
    float* w = dst + (size_t)t * Cc;
    #pragma unroll
    for (int j = 0; j < 6; j++) {
        int cc = lane + 32 * j;
        w[cc] = to_tf32((vals[j] - mu) * rs * g[cc] + b[cc]);
    }
}

// ---------------- tf32 tensor-core GEMM ----------------
// C[M,N] = A[M,K] @ B[N,K]^T (+bias, epilogue). CTA tile 128x192, 192 thr
// (2x3 warps, warp tile 64x64), K chunks of 32, 2-stage cp.async pipeline,
// ONE __syncthreads per chunk. N-tiling exact for all call sites.
// EPI: 0 = qkv (scale cols<192), 1 = residual add, 2 = gelu + tf32 round
constexpr int AS_W = 128 * 36, BS_W = 192 * 36, BUF_W = AS_W + BS_W;  // 11520
constexpr int GEMM_SMEM = BUF_W * 2 * 4;   // 92160 B (2 stages)

template <int NCOLS, int KDIM, int EPI>
__global__ void __launch_bounds__(192, 2)
gemm_kernel(const float* __restrict__ A, const float* __restrict__ Bw,
            const float* __restrict__ bias, const float* __restrict__ res,
            float* __restrict__ out) {
    extern __shared__ float smem_g[];
    const int tid = threadIdx.x, wid = tid >> 5, lane = tid & 31;
    const int wm = wid / 3, wn = wid % 3;
    const int n0 = blockIdx.x * 192;
    const int m0 = blockIdx.y * 128;
    constexpr int NC = KDIM / 32;
    const unsigned int sbase = (unsigned int)__cvta_generic_to_shared(smem_g);

    auto stage = [&](int buf, int c) {
        const int k0 = c * 32;
        const unsigned int sa = sbase + (unsigned)(buf * BUF_W) * 4u;
        #pragma unroll
        for (int i = 0; i < 6; i++) {
            int s = tid + i * 192;          // 1024 A segs (128 rows x 8 quads)
            if (s < 1024) {
                int row = s >> 3, cq = s & 7;
                cp16(sa + (unsigned)(row * 36 + cq * 4) * 4u,
                     A + (size_t)(m0 + row) * KDIM + k0 + cq * 4);
            }
        }
        const unsigned int sb = sbase + (unsigned)(buf * BUF_W + AS_W) * 4u;
        #pragma unroll
        for (int i = 0; i < 8; i++) {
            int s = tid + i * 192;          // 1536 B segs (192 rows x 8 quads)
            int row = s >> 3, cq = s & 7;
            cp16(sb + (unsigned)(row * 36 + cq * 4) * 4u,
                 Bw + (size_t)(n0 + row) * KDIM + k0 + cq * 4);
        }
    };

    float acc[4][8][4];
    #pragma unroll
    for (int mi = 0; mi < 4; mi++)
        #pragma unroll
        for (int ni = 0; ni < 8; ni++)
            #pragma unroll
            for (int q = 0; q < 4; q++) acc[mi][ni][q] = 0.f;

    stage(0, 0); cp_commit();

    const int la = lane >> 2, lb = lane & 3;
    for (int ch = 0; ch < NC; ch++) {
        cp_wait<0>();
        __syncthreads();     // buf ch ready; all warps done reading buf ch-1
        if (ch + 1 < NC) { stage((ch + 1) & 1, ch + 1); cp_commit(); }
        const unsigned int* As = (const unsigned int*)(smem_g + (ch & 1) * BUF_W);
        const unsigned int* Bs = As + AS_W;
        #pragma unroll
        for (int kk = 0; kk < 4; kk++) {
            unsigned int a[4][4], b[8][2];
            const int ac = kk * 8 + lb;
            #pragma unroll
            for (int mi = 0; mi < 4; mi++) {
                int base = (wm * 64 + mi * 16 + la) * 36 + ac;
                a[mi][0] = As[base];           a[mi][1] = As[base + 8 * 36];
                a[mi][2] = As[base + 4];       a[mi][3] = As[base + 8 * 36 + 4];
            }
            #pragma unroll
            for (int ni = 0; ni < 8; ni++) {
                int base = (wn * 64 + ni * 8 + la) * 36 + ac;
                b[ni][0] = Bs[base];           b[ni][1] = Bs[base + 4];
            }
            #pragma unroll
            for (int mi = 0; mi < 4; mi++)
                #pragma unroll
                for (int ni = 0; ni < 8; ni++) mma8(acc[mi][ni], a[mi], b[ni]);
        }
    }

    // ---- epilogue (tiling exact: no col bounds needed) ----
    const int er = m0 + wm * 64 + la;
    const int ec = n0 + wn * 64 + lb * 2;
    #pragma unroll
    for (int ni = 0; ni < 8; ni++) {
        const int col = ec + ni * 8;
        const float b0 = bias[col], b1 = bias[col + 1];
        #pragma unroll
        for (int mi = 0; mi < 4; mi++) {
            const int r0 = er + mi * 16;
            #pragma unroll
            for (int half = 0; half < 2; half++) {
                const int r = r0 + half * 8;
                float v0 = acc[mi][ni][half * 2 + 0] + b0;
                float v1 = acc[mi][ni][half * 2 + 1] + b1;
                const size_t off = (size_t)r * NCOLS + col;
                float2 o;
                if (EPI == 0) {             // qkv: scale q columns
                    if (col < 192) { v0 *= SCALE; v1 *= SCALE; }
                    o.x = v0; o.y = v1;
                } else if (EPI == 1) {      // residual add
                    float2 rv = *(const float2*)(res + off);
                    o.x = rv.x + v0; o.y = rv.y + v1;
                } else {                    // exact GELU, tf32 round
                    o.x = to_tf32(v0 * normcdff(v0));
                    o.y = to_tf32(v1 * normcdff(v1));
                }
                *(float2*)(out + off) = o;
            }
        }
    }
}

// ---------------- attention (per shifted window, sync-free tasks) -------
// Warp-task = (head, 7-query group); 42 tasks striped over 8 warps.
// K (stride 34) + V (stride 36) staged once; probs in per-warp smem region;
// only __syncwarp inside a task. One __syncthreads after staging.
constexpr int KSTR = 34, VSTR = 36;
constexpr int OK0 = 0;                          // 6*49*34 = 9996
constexpr int OV  = 9996;                       // 6*49*36 = 10584
constexpr int OPR = OV + 10584;                 // 20580: 8 warps * 352
constexpr int ORPB = OPR + 8 * 352;             // 23396: 1014
constexpr int OTOK = ORPB + 1014;               // 24410: 49
constexpr int OLAB = OTOK + 49;                 // 24459: 49
constexpr int ATT_SMEM_W = OLAB + 49;           // 24508 words
constexpr int ATT_SMEM = ATT_SMEM_W * 4;        // 98032 B

__global__ void __launch_bounds__(256)
attn_kernel(const float* __restrict__ qkv, const float* __restrict__ rpbt,
            float* __restrict__ att) {
    extern __shared__ float sm[];
    int* tok = (int*)(sm + OTOK);
    int* lab = (int*)(sm + OLAB);
    const int tid = threadIdx.x, wp = tid >> 5, lane = tid & 31;
    const int bw = blockIdx.x, img = bw >> 6, win = bw & 63;
    const int wr = win >> 3, wcw = win & 7;

    if (tid < Nn) {
        int r = tid / 7, c = tid % 7;
        int sy = (wr * 7 + r + 3) % 56, sx = (wcw * 7 + c + 3) % 56;
        tok[tid] = img * 3136 + sy * 56 + sx;
        int y = wr * 7 + r, xx = wcw * 7 + c;
        lab[tid] = ((y < 49) ? 0 : (y < 53 ? 1 : 2)) * 3 +
                   ((xx < 49) ? 0 : (xx < 53 ? 1 : 2));
    }
    for (int i = tid; i < 1014; i += 256) sm[ORPB + i] = rpbt[i];
    __syncthreads();   // tok[] ready for staging

    // stage K [h*49+j][34] (two float2 stores) and V [h*49+j][36] (float4)
    for (int e = tid; e < 49 * 48; e += 256) {
        int i = e / 48, c4 = e - i * 48;
        int col = c4 * 4, h = col >> 5, d = col & 31;
        float4 kv = *(const float4*)(qkv + (size_t)tok[i] * QKVN + 192 + col);
        float* kd = sm + OK0 + (h * 49 + i) * KSTR + d;
        *(float2*)(kd)     = make_float2(kv.x, kv.y);
        *(float2*)(kd + 2) = make_float2(kv.z, kv.w);
        float4 vv = *(const float4*)(qkv + (size_t)tok[i] * QKVN + 384 + col);
        *(float4*)(sm + OV + (h * 49 + i) * VSTR + d) = vv;
    }
    __syncthreads();

    float* prw = sm + OPR + wp * 352;   // this warp's prob scratch (7 x 50)

    for (int task = wp; task < 42; task += 8) {
        const int h = task / 7, ib = task - h * 7;

        // ---- K rows for this head into registers: lane j, j+32 ----
        unsigned long long k0r[16], k1r[16];
        {
            const unsigned long long* kp =
                (const unsigned long long*)(sm + OK0 + (h * 49 + lane) * KSTR);
            #pragma unroll
            for (int p = 0; p < 16; p++) k0r[p] = kp[p];
        }
        {
            int j1c = (lane < 17) ? lane + 32 : lane;   // clamp to valid row
            const unsigned long long* kp =
                (const unsigned long long*)(sm + OK0 + (h * 49 + j1c) * KSTR);
            #pragma unroll
            for (int p = 0; p < 16; p++) k1r[p] = kp[p];
        }
        const int rj0 = lane / 7, cj0 = lane % 7, lj0 = lab[lane];
        const int j1 = lane + 32;
        const int rj1 = j1 / 7, cj1 = j1 % 7;
        const int lj1 = (lane < 17) ? lab[j1] : 0;

        // ---- scores + softmax for 7 queries ----
        #pragma unroll
        for (int ii = 0; ii < 7; ii++) {
            int i = ib * 7 + ii;
            const unsigned long long* qp = (const unsigned long long*)(
                qkv + (size_t)tok[i] * QKVN + h * 32);
            unsigned long long a0 = 0ull, a1 = 0ull;
            #pragma unroll
            for (int p = 0; p < 16; p++) {
                unsigned long long qv = qp[p];
                fma2(a0, qv, k0r[p]);
                fma2(a1, qv, k1r[p]);
            }
            int ri = i / 7, ci = i % 7, li = lab[i];
            float s0 = sum2(a0) +
                sm[ORPB + ((ri - rj0 + 6) * 13 + (ci - cj0 + 6)) * 6 + h];
            if (lj0 != li) s0 -= 100.f;
            float s1;
            if (lane < 17) {
                s1 = sum2(a1) +
                    sm[ORPB + ((ri - rj1 + 6) * 13 + (ci - cj1 + 6)) * 6 + h];
                if (lj1 != li) s1 -= 100.f;
            } else s1 = __int_as_float(0xff800000);

            float m = fmaxf(s0, s1);
            #pragma unroll
            for (int o = 16; o; o >>= 1)
                m = fmaxf(m, __shfl_xor_sync(~0u, m, o));
            float e0 = __expf(s0 - m);
            float e1 = (lane < 17) ? __expf(s1 - m) : 0.f;
            float ssum = e0 + e1;
            #pragma unroll
            for (int o = 16; o; o >>= 1)
                ssum += __shfl_xor_sync(~0u, ssum, o);
            float inv = __frcp_rn(ssum);
            prw[ii * 50 + lane] = e0 * inv;
            if (lane < 17) prw[ii * 50 + j1] = e1 * inv;
        }
        __syncwarp();

        // ---- P @ V: lane = (jhalf 0..3, dquad 0..7) ----
        {
            const int dq = lane & 7, jh = lane >> 3;
            const int jbeg = jh * 13, jend = (jh < 3) ? jbeg + 13 : 49;
            float acc[7][4];
            #pragma unroll
            for (int ii = 0; ii < 7; ii++)
                #pragma unroll
                for (int q = 0; q < 4; q++) acc[ii][q] = 0.f;
            for (int j = jbeg; j < jend; j++) {
                float4 vv = *(const float4*)(sm + OV + (h * 49 + j) * VSTR + dq * 4);
                #pragma unroll
                for (int ii = 0; ii < 7; ii++) {
                    float p = prw[ii * 50 + j];
                    acc[ii][0] += p * vv.x; acc[ii][1] += p * vv.y;
                    acc[ii][2] += p * vv.z; acc[ii][3] += p * vv.w;
                }
            }
            #pragma unroll
            for (int ii = 0; ii < 7; ii++)
                #pragma unroll
                for (int q = 0; q < 4; q++) {
                    acc[ii][q] += __shfl_xor_sync(~0u, acc[ii][q], 8);
                    acc[ii][q] += __shfl_xor_sync(~0u, acc[ii][q], 16);
                }
            if (jh == 0) {
                #pragma unroll
                for (int ii = 0; ii < 7; ii++) {
                    int i = ib * 7 + ii;
                    float4 o;
                    o.x = to_tf32(acc[ii][0]); o.y = to_tf32(acc[ii][1]);
                    o.z = to_tf32(acc[ii][2]); o.w = to_tf32(acc[ii][3]);
                    *(float4*)(att + (size_t)tok[i] * Cc + h * 32 + dq * 4) = o;
                }
            }
        }
        __syncwarp();   // prw reuse safe for next task
    }
}

// ---------------- launch ----------------
extern "C" void kernel_launch(void* const* d_in, const int* in_sizes, int n_in,
                              void* d_out, int out_size) {
    const float* x     = (const float*)d_in[0];
    const float* n1g   = (const float*)d_in[1];
    const float* n1b   = (const float*)d_in[2];
    const float* qkvw  = (const float*)d_in[3];
    const float* qkvb  = (const float*)d_in[4];
    const float* projw = (const float*)d_in[5];
    const float* projb = (const float*)d_in[6];
    const float* rpbt  = (const float*)d_in[7];
    const float* n2g   = (const float*)d_in[8];
    const float* n2b   = (const float*)d_in[9];
    const float* fc1w  = (const float*)d_in[10];
    const float* fc1b  = (const float*)d_in[11];
    const float* fc2w  = (const float*)d_in[12];
    const float* fc2b  = (const float*)d_in[13];
    float* out = (float*)d_out;

    float *ln1, *qkvs, *atts, *hs, *ln2, *a1, *wr;
    cudaGetSymbolAddress((void**)&ln1,  g_ln1);
    cudaGetSymbolAddress((void**)&qkvs, g_qkv);
    cudaGetSymbolAddress((void**)&atts, g_att);
    cudaGetSymbolAddress((void**)&hs,   g_h);
    cudaGetSymbolAddress((void**)&ln2,  g_ln2);
    cudaGetSymbolAddress((void**)&a1,   g_a1);
    cudaGetSymbolAddress((void**)&wr,   g_wr);

    cudaFuncSetAttribute(gemm_kernel<QKVN, Cc, 0>,
                         cudaFuncAttributeMaxDynamicSharedMemorySize, GEMM_SMEM);
    cudaFuncSetAttribute(gemm_kernel<Cc, Cc, 1>,
                         cudaFuncAttributeMaxDynamicSharedMemorySize, GEMM_SMEM);
    cudaFuncSetAttribute(gemm_kernel<HID, Cc, 2>,
                         cudaFuncAttributeMaxDynamicSharedMemorySize, GEMM_SMEM);
    cudaFuncSetAttribute(gemm_kernel<Cc, HID, 1>,
                         cudaFuncAttributeMaxDynamicSharedMemorySize, GEMM_SMEM);
    cudaFuncSetAttribute(attn_kernel,
                         cudaFuncAttributeMaxDynamicSharedMemorySize, ATT_SMEM);

    round_kernel<<<(110592 + 255) / 256, 256>>>(qkvw, projw, fc1w, fc2w, wr);

    ln_kernel<<<Tt / 8, 256>>>(x, n1g, n1b, ln1);
    gemm_kernel<QKVN, Cc, 0><<<dim3(3, 784), 192, GEMM_SMEM>>>(
        ln1, wr + WO_QKV, qkvb, nullptr, qkvs);
    attn_kernel<<<2048, 256, ATT_SMEM>>>(qkvs, rpbt, atts);
    gemm_kernel<Cc, Cc, 1><<<dim3(1, 784), 192, GEMM_SMEM>>>(
        atts, wr + WO_PROJ, projb, x, hs);
    ln_kernel<<<Tt / 8, 256>>>(hs, n2g, n2b, ln2);
    gemm_kernel<HID, Cc, 2><<<dim3(4, 784), 192, GEMM_SMEM>>>(
        ln2, wr + WO_FC1, fc1b, nullptr, a1);
    gemm_kernel<Cc, HID, 1><<<dim3(1, 784), 192, GEMM_SMEM>>>(
        a1, wr + WO_FC2, fc2b, hs, out);
}